// round 1
// baseline (speedup 1.0000x reference)
#include <cuda_runtime.h>
#include <math.h>

#define B_   8
#define C_   64
#define H_   384
#define W_   384
#define TILE 64
#define HALO 4
#define SX_W 72          // TILE + 2*HALO
#define SR_W 65          // TILE + 1 (extra col for even-k blend)
#define NTHREADS 256

// Per-batch precomputed filter state (device-resident; params only exist on device)
__device__ float d_gw[B_][12];
__device__ int   d_kk[B_];

__global__ void prep_kernel(const float* __restrict__ params) {
    int b = threadIdx.x;
    if (b >= B_) return;
    float p0 = params[2 * b + 0];
    float p1 = params[2 * b + 1];
    float ki = truncf(p0);
    float s0 = 1.0f / (1.0f + expf(-ki));
    int k = (int)floorf(5.0f + 5.0f * s0);
    k = min(9, max(5, k));
    float s1 = 1.0f / (1.0f + expf(-p1));
    float sigma = 0.5f + 4.5f * s1;
    float inv2s2 = 1.0f / (2.0f * sigma * sigma);
    int half = k >> 1;
    float e[9];
    float sum = 0.0f;
    for (int u = 0; u < k; u++) {
        float c = (float)(u - half);
        e[u] = expf(-c * c * inv2s2);
        sum += e[u];
    }
    float inv = 1.0f / sum;
    for (int u = 0; u < 12; u++)
        d_gw[b][u] = (u < k) ? e[u] * inv : 0.0f;
    d_kk[b] = k;
}

template <int K>
__device__ __forceinline__ void blur_body(const float* __restrict__ x,
                                          float* __restrict__ out,
                                          float* sx, float* sr,
                                          int b, int c, int ti0, int tj0) {
    const int tid = threadIdx.x;
    constexpr int PAD = K / 2;
    constexpr int OFF = HALO - PAD;          // >= 0 for K <= 9
    constexpr bool EVEN = (K % 2 == 0);

    float g[K];
#pragma unroll
    for (int u = 0; u < K; u++) g[u] = d_gw[b][u];

    const float* xp = x + (size_t)(b * C_ + c) * (H_ * W_);

    // ---- Phase 0: load 72x72 input tile (zero-padded at image borders) ----
    for (int idx = tid; idx < SX_W * SX_W; idx += NTHREADS) {
        int r  = idx / SX_W;
        int cc = idx - r * SX_W;
        int gi = ti0 - HALO + r;
        int gj = tj0 - HALO + cc;
        float v = 0.0f;
        if (gi >= 0 && gi < H_ && gj >= 0 && gj < W_)
            v = xp[gi * W_ + gj];
        sx[idx] = v;
    }
    if (tid < 16)   sx[SX_W * SX_W + tid] = 0.0f;   // guard pad for K=9 slide
    if (tid < SR_W) sr[72 * SR_W + tid]   = 0.0f;   // guard row for K=9 slide
    __syncthreads();

    // ---- Phase 1: horizontal conv: sr[row][q] for row 0..71, q 0..64 ----
    // Register-sliding window: 5 outputs per task from K+4 loads.
    for (int tk = tid; tk < 72 * 13; tk += NTHREADS) {
        int row = tk / 13;
        int q0  = (tk - row * 13) * 5;
        float a[K + 4];
        const float* src = sx + row * SX_W + q0 + OFF;
#pragma unroll
        for (int m = 0; m < K + 4; m++) a[m] = src[m];
        float* dst = sr + row * SR_W + q0;
#pragma unroll
        for (int m = 0; m < 5; m++) {
            float acc = 0.0f;
#pragma unroll
            for (int v = 0; v < K; v++) acc = fmaf(g[v], a[m + v], acc);
            dst[m] = acc;
        }
    }
    __syncthreads();

    // ---- Phase 2: vertical conv into t grid (reuse sx buffer, stride SX_W) ----
    // t[p][q] for p,q in 0..64 (row/col 64 only meaningful for even K).
    for (int tk = tid; tk < 13 * 65; tk += NTHREADS) {
        int q  = tk % 65;
        int p0 = (tk / 65) * 5;
        float a[K + 4];
#pragma unroll
        for (int m = 0; m < K + 4; m++) a[m] = sr[(p0 + OFF + m) * SR_W + q];
#pragma unroll
        for (int m = 0; m < 5; m++) {
            float acc = 0.0f;
#pragma unroll
            for (int u = 0; u < K; u++) acc = fmaf(g[u], a[m + u], acc);
            sx[(p0 + m) * SX_W + q] = acc;
        }
    }
    __syncthreads();

    // ---- Phase 3: (even K) bilinear blend of 2x2 conv grid; (odd K) copy ----
    const float inv384 = 1.0f / 384.0f;
    float* op = out + (size_t)(b * C_ + c) * (H_ * W_);
    for (int idx = tid; idx < TILE * TILE; idx += NTHREADS) {
        int i = idx / TILE;
        int j = idx - i * TILE;
        int gi = ti0 + i, gj = tj0 + j;
        float o;
        if (EVEN) {
            // src coord = i + (i+0.5)/384 exactly -> i0 = i, frac = (i+0.5)/384
            float fi = ((float)gi + 0.5f) * inv384;
            float fj = ((float)gj + 0.5f) * inv384;
            float t00 = sx[i * SX_W + j];
            float t01 = sx[i * SX_W + j + 1];
            float t10 = sx[(i + 1) * SX_W + j];
            float t11 = sx[(i + 1) * SX_W + j + 1];
            float top = fmaf(fj, t01 - t00, t00);
            float bot = fmaf(fj, t11 - t10, t10);
            o = fmaf(fi, bot - top, top);
        } else {
            o = sx[i * SX_W + j];
        }
        op[gi * W_ + gj] = o;
    }
}

__global__ __launch_bounds__(NTHREADS)
void blur_kernel(const float* __restrict__ x, float* __restrict__ out) {
    __shared__ float sx[SX_W * SX_W + 16];
    __shared__ float sr[73 * SR_W];
    int bc = blockIdx.z;
    int b = bc >> 6;
    int c = bc & 63;
    int ti0 = blockIdx.y * TILE;
    int tj0 = blockIdx.x * TILE;
    int k = d_kk[b];
    switch (k) {
        case 5: blur_body<5>(x, out, sx, sr, b, c, ti0, tj0); break;
        case 6: blur_body<6>(x, out, sx, sr, b, c, ti0, tj0); break;
        case 7: blur_body<7>(x, out, sx, sr, b, c, ti0, tj0); break;
        case 8: blur_body<8>(x, out, sx, sr, b, c, ti0, tj0); break;
        default: blur_body<9>(x, out, sx, sr, b, c, ti0, tj0); break;
    }
}

extern "C" void kernel_launch(void* const* d_in, const int* in_sizes, int n_in,
                              void* d_out, int out_size) {
    const float* x      = (const float*)d_in[0];
    const float* params = (const float*)d_in[1];
    if (n_in >= 2 && in_sizes[0] < in_sizes[1]) {  // defensive: x is the big one
        const float* t = x; x = params; params = t;
    }
    float* out = (float*)d_out;

    prep_kernel<<<1, 32>>>(params);
    dim3 grid(W_ / TILE, H_ / TILE, B_ * C_);
    blur_kernel<<<grid, NTHREADS>>>(x, out);
}

// round 2
// speedup vs baseline: 1.2091x; 1.2091x over previous
#include <cuda_runtime.h>
#include <math.h>

#define B_   8
#define C_   64
#define H_   384
#define W_   384
#define TILE 64
#define HALO 4
#define SXW  72          // sx row stride (floats), 288B = 16B-aligned
#define SRW  68          // sr row stride (floats), 272B = 16B-aligned
#define NTH  256

// Per-batch precomputed filter state (params are device-resident only)
__device__ float d_gw[B_][12];
__device__ int   d_kk[B_];

__global__ void prep_kernel(const float* __restrict__ params) {
    int b = threadIdx.x;
    if (b >= B_) return;
    float p0 = params[2 * b + 0];
    float p1 = params[2 * b + 1];
    float ki = truncf(p0);
    float s0 = 1.0f / (1.0f + expf(-ki));
    int k = (int)floorf(5.0f + 5.0f * s0);
    k = min(9, max(5, k));
    float s1 = 1.0f / (1.0f + expf(-p1));
    float sigma = 0.5f + 4.5f * s1;
    float inv2s2 = 1.0f / (2.0f * sigma * sigma);
    int half = k >> 1;
    float e[9];
    float sum = 0.0f;
    for (int u = 0; u < k; u++) {
        float c = (float)(u - half);
        e[u] = expf(-c * c * inv2s2);
        sum += e[u];
    }
    float inv = 1.0f / sum;
    for (int u = 0; u < 12; u++)
        d_gw[b][u] = (u < k) ? e[u] * inv : 0.0f;
    d_kk[b] = k;
}

template <int K>
__device__ __forceinline__ void blur_body(const float* __restrict__ xp,
                                          float* __restrict__ op,
                                          float* sx, float* sr,
                                          const float* __restrict__ gw,
                                          int ti0, int tj0) {
    const int tid = threadIdx.x;
    constexpr int PAD  = K / 2;
    constexpr int OFF  = HALO - PAD;          // 0..2 for K in 5..9
    constexpr bool EVEN = (K % 2 == 0);

    float g[K];
#pragma unroll
    for (int u = 0; u < K; u++) g[u] = gw[u];

    // ---- Phase 0: load 72x72 input tile as float4 (zero at borders) ----
    for (int t = tid; t < 72 * 18; t += NTH) {
        int r  = t / 18;
        int cc = t - r * 18;
        int gi = ti0 - HALO + r;
        int gj = tj0 - HALO + cc * 4;        // multiple of 4: float4 never straddles border
        float4 v = make_float4(0.f, 0.f, 0.f, 0.f);
        if (gi >= 0 && gi < H_ && gj >= 0 && gj < W_)
            v = *reinterpret_cast<const float4*>(xp + gi * W_ + gj);
        *reinterpret_cast<float4*>(sx + r * SXW + cc * 4) = v;
    }
    // zero sr guard rows 72..75 (read by even-K vertical slide for unused outputs)
    for (int t = tid; t < 4 * SRW; t += NTH) sr[72 * SRW + t] = 0.0f;
    __syncthreads();

    // ---- Phase 1: horizontal conv, vectorized. sr[r][q], r 0..71, q 0..67 ----
    for (int t = tid; t < 72 * 17; t += NTH) {
        int r  = t / 17;
        int q0 = (t - r * 17) * 4;
        const float* src = sx + r * SXW + q0;
        float4 A = *reinterpret_cast<const float4*>(src);
        float4 Bv = *reinterpret_cast<const float4*>(src + 4);
        float4 Cv = *reinterpret_cast<const float4*>(src + 8);
        float a[12] = {A.x, A.y, A.z, A.w, Bv.x, Bv.y, Bv.z, Bv.w,
                       Cv.x, Cv.y, Cv.z, Cv.w};
        float o[4];
#pragma unroll
        for (int m = 0; m < 4; m++) {
            float acc = 0.0f;
#pragma unroll
            for (int v = 0; v < K; v++) acc = fmaf(g[v], a[m + OFF + v], acc);
            o[m] = acc;
        }
        *reinterpret_cast<float4*>(sr + r * SRW + q0) =
            make_float4(o[0], o[1], o[2], o[3]);
    }
    __syncthreads();

    // ---- Phase 2: vertical conv, vectorized across columns ----
    if (!EVEN) {
        // direct to global: rows 0..63, cols 0..63. Exactly 256 tasks.
        int rg = tid >> 4;
        int cg = tid & 15;
        int p0 = rg * 4;
        int j0 = cg * 4;
        float4 acc[4];
#pragma unroll
        for (int m = 0; m < 4; m++) acc[m] = make_float4(0.f, 0.f, 0.f, 0.f);
#pragma unroll
        for (int r = 0; r < K + 3; r++) {
            float4 w = *reinterpret_cast<const float4*>(sr + (p0 + OFF + r) * SRW + j0);
#pragma unroll
            for (int m = 0; m < 4; m++) {
                if (r >= m && r - m < K) {
                    float gv = g[r - m];
                    acc[m].x = fmaf(gv, w.x, acc[m].x);
                    acc[m].y = fmaf(gv, w.y, acc[m].y);
                    acc[m].z = fmaf(gv, w.z, acc[m].z);
                    acc[m].w = fmaf(gv, w.w, acc[m].w);
                }
            }
        }
#pragma unroll
        for (int m = 0; m < 4; m++)
            *reinterpret_cast<float4*>(op + (size_t)(ti0 + p0 + m) * W_ + tj0 + j0) = acc[m];
    } else {
        // t grid rows 0..67, cols 0..67 into sx (rows >64 / cols >64 unused)
        for (int t = tid; t < 17 * 17; t += NTH) {
            int rg = t / 17;
            int cg = t - rg * 17;
            int p0 = rg * 4;
            int j0 = cg * 4;
            float4 acc[4];
#pragma unroll
            for (int m = 0; m < 4; m++) acc[m] = make_float4(0.f, 0.f, 0.f, 0.f);
#pragma unroll
            for (int r = 0; r < K + 3; r++) {
                float4 w = *reinterpret_cast<const float4*>(sr + (p0 + OFF + r) * SRW + j0);
#pragma unroll
                for (int m = 0; m < 4; m++) {
                    if (r >= m && r - m < K) {
                        float gv = g[r - m];
                        acc[m].x = fmaf(gv, w.x, acc[m].x);
                        acc[m].y = fmaf(gv, w.y, acc[m].y);
                        acc[m].z = fmaf(gv, w.z, acc[m].z);
                        acc[m].w = fmaf(gv, w.w, acc[m].w);
                    }
                }
            }
#pragma unroll
            for (int m = 0; m < 4; m++)
                *reinterpret_cast<float4*>(sx + (p0 + m) * SXW + j0) = acc[m];
        }
        __syncthreads();

        // ---- Phase 3: bilinear blend of 2x2 t-grid, vectorized ----
        const float inv384 = 1.0f / 384.0f;
        for (int t = tid; t < 64 * 16; t += NTH) {
            int i  = t >> 4;
            int j0 = (t & 15) * 4;
            const float* r0 = sx + i * SXW + j0;
            const float* r1 = sx + (i + 1) * SXW + j0;
            float4 t00 = *reinterpret_cast<const float4*>(r0);
            float  t0e = r0[4];
            float4 t10 = *reinterpret_cast<const float4*>(r1);
            float  t1e = r1[4];
            int gi = ti0 + i;
            int gj = tj0 + j0;
            float fi = ((float)gi + 0.5f) * inv384;
            float o[4];
            float a0[5] = {t00.x, t00.y, t00.z, t00.w, t0e};
            float a1[5] = {t10.x, t10.y, t10.z, t10.w, t1e};
#pragma unroll
            for (int m = 0; m < 4; m++) {
                float fj  = ((float)(gj + m) + 0.5f) * inv384;
                float top = fmaf(fj, a0[m + 1] - a0[m], a0[m]);
                float bot = fmaf(fj, a1[m + 1] - a1[m], a1[m]);
                o[m] = fmaf(fi, bot - top, top);
            }
            *reinterpret_cast<float4*>(op + (size_t)gi * W_ + gj) =
                make_float4(o[0], o[1], o[2], o[3]);
        }
    }
}

__global__ __launch_bounds__(NTH)
void blur_kernel(const float* __restrict__ x, float* __restrict__ out) {
    __shared__ float sx[72 * SXW + 16];   // input tile / t-grid (+ slide guard)
    __shared__ float sr[76 * SRW];        // horizontal result (+4 guard rows)
    int bc = blockIdx.z;
    int b = bc >> 6;
    int c = bc & 63;
    int ti0 = blockIdx.y * TILE;
    int tj0 = blockIdx.x * TILE;
    const float* xp = x + (size_t)(b * C_ + c) * (H_ * W_);
    float* op = out + (size_t)(b * C_ + c) * (H_ * W_);
    const float* gw = d_gw[b];
    switch (d_kk[b]) {
        case 5: blur_body<5>(xp, op, sx, sr, gw, ti0, tj0); break;
        case 6: blur_body<6>(xp, op, sx, sr, gw, ti0, tj0); break;
        case 7: blur_body<7>(xp, op, sx, sr, gw, ti0, tj0); break;
        case 8: blur_body<8>(xp, op, sx, sr, gw, ti0, tj0); break;
        default: blur_body<9>(xp, op, sx, sr, gw, ti0, tj0); break;
    }
}

extern "C" void kernel_launch(void* const* d_in, const int* in_sizes, int n_in,
                              void* d_out, int out_size) {
    const float* x      = (const float*)d_in[0];
    const float* params = (const float*)d_in[1];
    if (n_in >= 2 && in_sizes[0] < in_sizes[1]) {
        const float* t = x; x = params; params = t;
    }
    float* out = (float*)d_out;

    prep_kernel<<<1, 32>>>(params);
    dim3 grid(W_ / TILE, H_ / TILE, B_ * C_);
    blur_kernel<<<grid, NTH>>>(x, out);
}